// round 2
// baseline (speedup 1.0000x reference)
#include <cuda_runtime.h>
#include <math.h>

#define BB 32
#define NN 512
#define FF 1024
#define HH 8
#define DD 128

// Scratch (device globals: allocation-free per harness rules)
__device__ float g_gate[BB * FF];            // 128 KB
__device__ float g_wqt[FF * FF];             // 4 MB  : Wq transposed to [f, h*128+d]
__device__ float g_qg[BB * NN * FF];         // 64 MB : (Q + bq) * gate * scale, layout [b,n,h*d]
__device__ float g_kg[BB * NN * FF];         // 64 MB : x1 * gate
__device__ float g_vb[BB * NN * FF];         // 64 MB : attention context, layout [b,n,h*d]

// ---------------------------------------------------------------------------
// gate[b,f] = mean_n x2[b,n,f]
__global__ void gate_kernel(const float* __restrict__ x2, float* __restrict__ gate) {
    int b = blockIdx.x;
    int f = threadIdx.x;  // 1024 threads
    const float* p = x2 + (size_t)b * NN * FF + f;
    float s = 0.f;
#pragma unroll 8
    for (int n = 0; n < NN; n++) s += p[(size_t)n * FF];
    gate[b * FF + f] = s * (1.0f / NN);
}

// Wqt[f*1024 + h*128 + d] = Wq[h][f][d]
__global__ void wqt_kernel(const float* __restrict__ Wq, float* __restrict__ Wqt) {
    int idx = blockIdx.x * 256 + threadIdx.x;
    int c = idx & (FF - 1);
    int f = idx >> 10;
    int h = c >> 7, d = c & (DD - 1);
    Wqt[idx] = Wq[((size_t)h * FF + f) * DD + d];
}

// Kg = x1 * gate (broadcast over n)
__global__ void kg_kernel(const float* __restrict__ x1, const float* __restrict__ gate,
                          float* __restrict__ Kg) {
    size_t i = (size_t)blockIdx.x * 256 + threadIdx.x;
    int c = (int)(i & (FF - 1));
    int b = (int)(i >> 19);  // NN*FF = 2^19
    Kg[i] = x1[i] * gate[b * FF + c];
}

// ---------------------------------------------------------------------------
// Tiled SGEMM: C[M,N] = A[M,K] @ B[K,N] (or A @ B^T when TB, B given as [N,K])
// BM=BN=128, BK=8, 256 threads, 8x8 per thread. blockIdx.z selects (b,h) slice.
// MODE: 0 = Q-proj epilogue  ((acc+bq[c]) * gate[b,c] * scale)
//       1 = aff epilogue     (mask ? -1e9 : acc)  [TB]
//       2 = plain store      (att @ V)
//       3 = out epilogue     (relu(acc+bl[c]) + x1[r,c])
// mask is the bool (B,1,N,N) array widened by the harness to a 4-byte type
// (int32 or float32) — both encode "true" as a nonzero 32-bit word.
template <int MODE, bool TB>
__global__ void __launch_bounds__(256, 2)
gemm_k(const float* __restrict__ Ab, const float* __restrict__ Bb, float* __restrict__ Cb,
       int M, int N, int K, int lda, int ldb, int ldc,
       long sAb, long sAh, long sBb, long sBh, long sCb, long sCh,
       const float* __restrict__ e0, const float* __restrict__ e1,
       const unsigned int* __restrict__ maskb) {
    __shared__ float As[8][128];
    __shared__ float Bs[8][128];

    int z = blockIdx.z;
    const float* A = Ab + (long)(z >> 3) * sAb + (long)(z & 7) * sAh;
    const float* Bp = Bb + (long)(z >> 3) * sBb + (long)(z & 7) * sBh;
    float* C = Cb + (long)(z >> 3) * sCb + (long)(z & 7) * sCh;
    const unsigned int* msk = (MODE == 1) ? (maskb + (size_t)(z >> 3) * NN * NN) : nullptr;

    int bm = blockIdx.y * 128;
    int bn = blockIdx.x * 128;
    int tid = threadIdx.x;
    int tx = tid & 15, ty = tid >> 4;

    float acc[8][8];
#pragma unroll
    for (int i = 0; i < 8; i++)
#pragma unroll
        for (int j = 0; j < 8; j++) acc[i][j] = 0.f;

    int ar = tid >> 1, ac = (tid & 1) * 4;
    int br, bc;
    if (TB) { br = tid >> 1; bc = (tid & 1) * 4; }
    else    { br = tid >> 5; bc = (tid & 31) * 4; }

    for (int k0 = 0; k0 < K; k0 += 8) {
        float4 av = *reinterpret_cast<const float4*>(A + (size_t)(bm + ar) * lda + k0 + ac);
        As[ac + 0][ar] = av.x;
        As[ac + 1][ar] = av.y;
        As[ac + 2][ar] = av.z;
        As[ac + 3][ar] = av.w;
        if (TB) {
            float4 bv = *reinterpret_cast<const float4*>(Bp + (size_t)(bn + br) * ldb + k0 + bc);
            Bs[bc + 0][br] = bv.x;
            Bs[bc + 1][br] = bv.y;
            Bs[bc + 2][br] = bv.z;
            Bs[bc + 3][br] = bv.w;
        } else {
            float4 bv = *reinterpret_cast<const float4*>(Bp + (size_t)(k0 + br) * ldb + bn + bc);
            *reinterpret_cast<float4*>(&Bs[br][bc]) = bv;
        }
        __syncthreads();

#pragma unroll
        for (int kk = 0; kk < 8; kk++) {
            float a[8], b[8];
            *reinterpret_cast<float4*>(&a[0]) = *reinterpret_cast<const float4*>(&As[kk][ty * 8]);
            *reinterpret_cast<float4*>(&a[4]) = *reinterpret_cast<const float4*>(&As[kk][ty * 8 + 4]);
            *reinterpret_cast<float4*>(&b[0]) = *reinterpret_cast<const float4*>(&Bs[kk][tx * 8]);
            *reinterpret_cast<float4*>(&b[4]) = *reinterpret_cast<const float4*>(&Bs[kk][tx * 8 + 4]);
#pragma unroll
            for (int i = 0; i < 8; i++)
#pragma unroll
                for (int j = 0; j < 8; j++) acc[i][j] += a[i] * b[j];
        }
        __syncthreads();
    }

    const float SCALE = 0.08838834764831845f;  // 1/sqrt(128)
#pragma unroll
    for (int i = 0; i < 8; i++) {
        int r = bm + ty * 8 + i;
#pragma unroll
        for (int j = 0; j < 8; j++) {
            int c = bn + tx * 8 + j;
            float v = acc[i][j];
            if (MODE == 0) {
                v = (v + e0[c]) * e1[((r >> 9) << 10) + c] * SCALE;
            } else if (MODE == 1) {
                v = (msk[(size_t)r * NN + c] != 0u) ? -1e9f : v;
            } else if (MODE == 3) {
                v = fmaxf(v + e0[c], 0.f) + e1[(size_t)r * FF + c];
            }
            C[(size_t)r * ldc + c] = v;
        }
    }
}

// ---------------------------------------------------------------------------
// In-place row softmax over att rows of length 512. One warp per row.
__global__ void softmax_kernel(float* __restrict__ att) {
    int row = blockIdx.x * 8 + (threadIdx.x >> 5);
    int lane = threadIdx.x & 31;
    float* p = att + (size_t)row * NN;
    float v[16];
    float mx = -INFINITY;
#pragma unroll
    for (int i = 0; i < 16; i++) {
        v[i] = p[lane + i * 32];
        mx = fmaxf(mx, v[i]);
    }
#pragma unroll
    for (int o = 16; o; o >>= 1) mx = fmaxf(mx, __shfl_xor_sync(0xffffffffu, mx, o));
    float s = 0.f;
#pragma unroll
    for (int i = 0; i < 16; i++) {
        v[i] = __expf(v[i] - mx);
        s += v[i];
    }
#pragma unroll
    for (int o = 16; o; o >>= 1) s += __shfl_xor_sync(0xffffffffu, s, o);
    float inv = 1.f / s;
#pragma unroll
    for (int i = 0; i < 16; i++) p[lane + i * 32] = v[i] * inv;
}

// ---------------------------------------------------------------------------
extern "C" void kernel_launch(void* const* d_in, const int* in_sizes, int n_in,
                              void* d_out, int out_size) {
    const float* x1 = (const float*)d_in[0];
    const float* x2 = (const float*)d_in[1];
    // d_in[2] = adj, d_in[3] = bias : unused by the reference forward
    const unsigned int* mask = (const unsigned int*)d_in[4];
    const float* Wq = (const float*)d_in[5];
    const float* bq = (const float*)d_in[6];
    const float* Wl = (const float*)d_in[7];
    const float* bl = (const float*)d_in[8];

    float* out_x = (float*)d_out;
    // outputs are (xout, att) concatenated; att is the trailing B*H*N*N floats
    float* out_att = (float*)d_out + ((size_t)out_size - (size_t)BB * HH * NN * NN);

    float *p_gate, *p_wqt, *p_qg, *p_kg, *p_vb;
    cudaGetSymbolAddress((void**)&p_gate, g_gate);
    cudaGetSymbolAddress((void**)&p_wqt, g_wqt);
    cudaGetSymbolAddress((void**)&p_qg, g_qg);
    cudaGetSymbolAddress((void**)&p_kg, g_kg);
    cudaGetSymbolAddress((void**)&p_vb, g_vb);

    // 1) gate = mean(x2, axis=1)
    gate_kernel<<<BB, 1024>>>(x2, p_gate);
    // 2) transpose Wq -> [f, h*128+d]
    wqt_kernel<<<FF * FF / 256, 256>>>(Wq, p_wqt);
    // 3) Kg = x1 * gate
    kg_kernel<<<(BB * NN * FF) / 256, 256>>>(x1, p_gate, p_kg);
    // 4) Qg = (x1 @ Wqt + bq) * gate * scale     [16384 x 1024 x 1024]
    gemm_k<0, false><<<dim3(8, 128, 1), 256>>>(
        x1, p_wqt, p_qg, 16384, 1024, 1024, 1024, 1024, 1024,
        0, 0, 0, 0, 0, 0, bq, p_gate, nullptr);
    // 5) aff = Qg @ Kg^T per (b,h), mask fused   [512 x 512 x 128] x 256
    gemm_k<1, true><<<dim3(4, 4, 256), 256>>>(
        p_qg, p_kg, out_att, 512, 512, 128, 1024, 1024, 512,
        (long)NN * FF, DD, (long)NN * FF, DD, (long)HH * NN * NN, (long)NN * NN,
        nullptr, nullptr, mask);
    // 6) softmax rows of att (in place)
    softmax_kernel<<<(BB * HH * NN) / 8, 256>>>(out_att);
    // 7) V_ = att @ V per (b,h)                  [512 x 128 x 512] x 256
    gemm_k<2, false><<<dim3(1, 4, 256), 256>>>(
        out_att, x1, p_vb, 512, 128, 512, 512, 1024, 1024,
        (long)HH * NN * NN, (long)NN * NN, (long)NN * FF, DD, (long)NN * FF, DD,
        nullptr, nullptr, nullptr);
    // 8) xout = relu(V_ @ Wl + bl) + x1          [16384 x 1024 x 1024]
    gemm_k<3, false><<<dim3(8, 128, 1), 256>>>(
        p_vb, Wl, out_x, 16384, 1024, 1024, 1024, 1024, 1024,
        0, 0, 0, 0, 0, 0, bl, x1, nullptr);
}

// round 5
// speedup vs baseline: 2.3149x; 2.3149x over previous
#include <cuda_runtime.h>
#include <cuda_bf16.h>
#include <math.h>
#include <cstdint>

#define BB 32
#define NN 512
#define FF 1024
#define HH 8
#define DD 128

// ---------------------------------------------------------------------------
// Device scratch (allocation-free)
__device__ unsigned short g_x1h[BB * NN * FF], g_x1l[BB * NN * FF];
__device__ unsigned short g_kgh[BB * NN * FF], g_kgl[BB * NN * FF];
__device__ unsigned short g_qgh[BB * NN * FF], g_qgl[BB * NN * FF];
__device__ unsigned short g_vth[BB * NN * FF], g_vtl[BB * NN * FF];
__device__ unsigned short g_vbh[BB * NN * FF], g_vbl[BB * NN * FF];
__device__ unsigned short g_wqth[FF * FF], g_wqtl[FF * FF];
__device__ unsigned short g_wlth[FF * FF], g_wltl[FF * FF];
__device__ unsigned short g_atth[(size_t)BB * HH * NN * NN];
__device__ unsigned short g_attl[(size_t)BB * HH * NN * NN];
__device__ float g_gate[BB * FF];

__device__ __forceinline__ void split2(float v, unsigned short& h, unsigned short& l) {
    __nv_bfloat16 hh = __float2bfloat16(v);
    __nv_bfloat16 ll = __float2bfloat16(v - __bfloat162float(hh));
    h = *reinterpret_cast<unsigned short*>(&hh);
    l = *reinterpret_cast<unsigned short*>(&ll);
}

__device__ __forceinline__ uint32_t smem_u32(const void* p) {
    uint32_t a;
    asm("{ .reg .u64 t; cvta.to.shared.u64 t, %1; cvt.u32.u64 %0, t; }" : "=r"(a) : "l"(p));
    return a;
}
__device__ __forceinline__ void cpa16(uint32_t dst, const void* src) {
    asm volatile("cp.async.cg.shared.global [%0], [%1], 16;" :: "r"(dst), "l"(src));
}
#define CP_COMMIT() asm volatile("cp.async.commit_group;" ::: "memory")
#define CP_WAIT(n) asm volatile("cp.async.wait_group %0;" :: "n"(n) : "memory")

__device__ __forceinline__ void ldsm4(uint32_t* r, uint32_t addr) {
    asm volatile("ldmatrix.sync.aligned.m8n8.x4.shared.b16 {%0,%1,%2,%3}, [%4];"
                 : "=r"(r[0]), "=r"(r[1]), "=r"(r[2]), "=r"(r[3]) : "r"(addr));
}
__device__ __forceinline__ void mma_bf16(float* d, const uint32_t* a, const uint32_t* b) {
    asm volatile(
        "mma.sync.aligned.m16n8k16.row.col.f32.bf16.bf16.f32 "
        "{%0,%1,%2,%3}, {%4,%5,%6,%7}, {%8,%9}, {%0,%1,%2,%3};"
        : "+f"(d[0]), "+f"(d[1]), "+f"(d[2]), "+f"(d[3])
        : "r"(a[0]), "r"(a[1]), "r"(a[2]), "r"(a[3]), "r"(b[0]), "r"(b[1]));
}

// ---------------------------------------------------------------------------
// Small kernels
__global__ void gate_kernel(const float* __restrict__ x2, float* __restrict__ gate) {
    int b = blockIdx.x;
    int f = threadIdx.x;
    const float* p = x2 + (size_t)b * NN * FF + f;
    float s = 0.f;
#pragma unroll 8
    for (int n = 0; n < NN; n++) s += p[(size_t)n * FF];
    gate[b * FF + f] = s * (1.0f / NN);
}

__global__ void conv_x1(const float* __restrict__ x1, const float* __restrict__ gate,
                        unsigned short* xh, unsigned short* xl,
                        unsigned short* kh, unsigned short* kl) {
    size_t i = (size_t)blockIdx.x * 256 + threadIdx.x;
    int c = (int)(i & (FF - 1));
    int b = (int)(i >> 19);
    float v = x1[i];
    split2(v, xh[i], xl[i]);
    split2(v * gate[b * FF + c], kh[i], kl[i]);
}

__global__ void conv_wq(const float* __restrict__ Wq, unsigned short* oh, unsigned short* ol) {
    int idx = blockIdx.x * 256 + threadIdx.x;
    int k = idx & (FF - 1);
    int n = idx >> 10;
    int h = n >> 7, d = n & (DD - 1);
    split2(Wq[((size_t)h * FF + k) * DD + d], oh[idx], ol[idx]);
}

__global__ void conv_wl(const float* __restrict__ Wl, unsigned short* oh, unsigned short* ol) {
    int idx = blockIdx.x * 256 + threadIdx.x;
    int k = idx & (FF - 1);
    int n = idx >> 10;
    split2(Wl[(size_t)k * FF + n], oh[idx], ol[idx]);
}

// Vt[z=(b,h)][d][m] = x1[b, m, h*128+d]
__global__ void conv_vt(const float* __restrict__ x1, unsigned short* oh, unsigned short* ol) {
    __shared__ float s[32][33];
    int z = blockIdx.z, b = z >> 3, h = z & 7;
    int m0 = blockIdx.x * 32, d0 = blockIdx.y * 32;
    const float* src = x1 + (size_t)b * NN * FF + h * DD;
    int tx = threadIdx.x, ty = threadIdx.y;
#pragma unroll
    for (int i = 0; i < 32; i += 8)
        s[ty + i][tx] = src[(size_t)(m0 + ty + i) * FF + d0 + tx];
    __syncthreads();
    size_t zo = (size_t)z * DD * NN;
#pragma unroll
    for (int i = 0; i < 32; i += 8) {
        float v = s[tx][ty + i];
        size_t o = zo + (size_t)(d0 + ty + i) * NN + m0 + tx;
        split2(v, oh[o], ol[o]);
    }
}

// softmax rows of att (in place, fp32) + emit bf16 hi/lo planes
__global__ void softmax_kernel(float* __restrict__ att,
                               unsigned short* __restrict__ ah,
                               unsigned short* __restrict__ al) {
    int row = blockIdx.x * 8 + (threadIdx.x >> 5);
    int lane = threadIdx.x & 31;
    size_t base = (size_t)row * NN;
    float* p = att + base;
    float v[16];
    float mx = -INFINITY;
#pragma unroll
    for (int i = 0; i < 16; i++) {
        v[i] = p[lane + i * 32];
        mx = fmaxf(mx, v[i]);
    }
#pragma unroll
    for (int o = 16; o; o >>= 1) mx = fmaxf(mx, __shfl_xor_sync(0xffffffffu, mx, o));
    float s = 0.f;
#pragma unroll
    for (int i = 0; i < 16; i++) {
        v[i] = __expf(v[i] - mx);
        s += v[i];
    }
#pragma unroll
    for (int o = 16; o; o >>= 1) s += __shfl_xor_sync(0xffffffffu, s, o);
    float inv = 1.f / s;
#pragma unroll
    for (int i = 0; i < 16; i++) {
        float w = v[i] * inv;
        int c = lane + i * 32;
        p[c] = w;
        split2(w, ah[base + c], al[base + c]);
    }
}

// ---------------------------------------------------------------------------
// Warp-MMA bf16x3 GEMM. CTA tile 128x128, KC=32, 8 warps (4m x 2n),
// double-buffered cp.async, XOR-swizzled smem for conflict-free ldmatrix.
// A[M,K] and B[N,K] hi/lo bf16 planes. MODE epilogues as before.
#define KC 32
#define PLANE_BYTES 8192          // 128 rows * 64 B
#define STAGE_BYTES 32768         // 4 planes
#define SMEM_BYTES 65536          // 2 stages

__device__ __forceinline__ void store_pair_bf16(unsigned short* Ch, unsigned short* Cl,
                                                size_t co, float v0, float v1) {
    unsigned short h0, l0, h1, l1;
    split2(v0, h0, l0);
    split2(v1, h1, l1);
    *reinterpret_cast<uint32_t*>(Ch + co) = (uint32_t)h0 | ((uint32_t)h1 << 16);
    *reinterpret_cast<uint32_t*>(Cl + co) = (uint32_t)l0 | ((uint32_t)l1 << 16);
}

template <int MODE>
__global__ void __launch_bounds__(256)
mma_gemm(const unsigned short* __restrict__ Ah, const unsigned short* __restrict__ Al,
         int lda, long sAz, long sAh2,
         const unsigned short* __restrict__ Bh, const unsigned short* __restrict__ Bl,
         int ldb, long sBz, long sBh2,
         int K,
         float* __restrict__ Cf, unsigned short* __restrict__ Ch, unsigned short* __restrict__ Cl,
         int ldc, long sCz, long sCh2,
         const float* __restrict__ e0, const float* __restrict__ e1,
         const unsigned int* __restrict__ maskb) {
    extern __shared__ char smem[];
    uint32_t sbase = smem_u32(smem);
    int tid = threadIdx.x;
    int lid = tid & 31, wid = tid >> 5;
    int wm = wid & 3, wn = wid >> 2;

    int z = blockIdx.z;
    const unsigned short* pAh = Ah + (long)(z >> 3) * sAz + (long)(z & 7) * sAh2;
    const unsigned short* pAl = Al + (long)(z >> 3) * sAz + (long)(z & 7) * sAh2;
    const unsigned short* pBh = Bh + (long)(z >> 3) * sBz + (long)(z & 7) * sBh2;
    const unsigned short* pBl = Bl + (long)(z >> 3) * sBz + (long)(z & 7) * sBh2;
    long zC = (long)(z >> 3) * sCz + (long)(z & 7) * sCh2;
    const unsigned int* msk = (MODE == 1) ? (maskb + (size_t)(z >> 3) * NN * NN) : nullptr;

    int bm = blockIdx.y * 128;
    int bn = blockIdx.x * 128;

    float acc[2][8][4];
#pragma unroll
    for (int i = 0; i < 2; i++)
#pragma unroll
        for (int j = 0; j < 8; j++)
#pragma unroll
            for (int k = 0; k < 4; k++) acc[i][j][k] = 0.f;

    // ldmatrix per-lane addressing (swizzle: chunk' = chunk ^ ((row>>1)&3))
    int aRow = ((lid >> 3) & 1) * 8 + (lid & 7);   // rows within 16-row tile
    int aK = lid >> 4;                              // k8 within k16
    int bRow = ((lid >> 4) & 1) * 8 + (lid & 7);
    int bK = (lid >> 3) & 1;
    uint32_t offA0 = (uint32_t)(wm * 32 + aRow) * 64;
    uint32_t offA1 = offA0 + 16 * 64;
    uint32_t swzA = (uint32_t)((aRow >> 1) & 3);
    uint32_t offB[4];
#pragma unroll
    for (int p = 0; p < 4; p++) offB[p] = (uint32_t)(wn * 64 + p * 16 + bRow) * 64;
    uint32_t swzB = (uint32_t)((bRow >> 1) & 3);

    // loader mapping: each thread copies 2x16B per plane
    int lrow = tid >> 2, lkc = tid & 3;

#define LOAD_PLANE(dstoff, src, ld, row0, k0)                                         \
    {                                                                                 \
        _Pragma("unroll") for (int i = 0; i < 2; i++) {                               \
            int row = lrow + i * 64;                                                  \
            uint32_t d = (dstoff) + (uint32_t)row * 64 +                              \
                         ((uint32_t)(lkc ^ ((row >> 1) & 3)) << 4);                   \
            cpa16(d, (src) + (size_t)((row0) + row) * (ld) + (k0) + lkc * 8);         \
        }                                                                             \
    }

#define LOAD_STAGE(st, k0)                                                  \
    {                                                                       \
        uint32_t sb_ = sbase + (uint32_t)(st) * STAGE_BYTES;                \
        LOAD_PLANE(sb_ + 0, pAh, lda, bm, k0);                              \
        LOAD_PLANE(sb_ + PLANE_BYTES, pAl, lda, bm, k0);                    \
        LOAD_PLANE(sb_ + 2 * PLANE_BYTES, pBh, ldb, bn, k0);                \
        LOAD_PLANE(sb_ + 3 * PLANE_BYTES, pBl, ldb, bn, k0);                \
    }

    int nch = K >> 5;
    LOAD_STAGE(0, 0);
    CP_COMMIT();

    for (int c = 0; c < nch; c++) {
        if (c + 1 < nch) {
            LOAD_STAGE((c + 1) & 1, (c + 1) * KC);
            CP_COMMIT();
            CP_WAIT(1);
        } else {
            CP_WAIT(0);
        }
        __syncthreads();

        uint32_t ss = sbase + (uint32_t)(c & 1) * STAGE_BYTES;
#pragma unroll
        for (int s = 0; s < 2; s++) {
            uint32_t aH0[4], aH1[4], aL0[4], aL1[4];
            uint32_t ka = ((uint32_t)(s * 2 + aK) ^ swzA) << 4;
            ldsm4(aH0, ss + offA0 + ka);
            ldsm4(aH1, ss + offA1 + ka);
            ldsm4(aL0, ss + PLANE_BYTES + offA0 + ka);
            ldsm4(aL1, ss + PLANE_BYTES + offA1 + ka);
            uint32_t bHf[16], bLf[16];
            uint32_t kb = ((uint32_t)(s * 2 + bK) ^ swzB) << 4;
#pragma unroll
            for (int p = 0; p < 4; p++) {
                ldsm4(bHf + p * 4, ss + 2 * PLANE_BYTES + offB[p] + kb);
                ldsm4(bLf + p * 4, ss + 3 * PLANE_BYTES + offB[p] + kb);
            }
#pragma unroll
            for (int nt = 0; nt < 8; nt++) {
                const uint32_t* bh = bHf + nt * 2;
                const uint32_t* bl = bLf + nt * 2;
                mma_bf16(acc[0][nt], aH0, bh);
                mma_bf16(acc[1][nt], aH1, bh);
                mma_bf16(acc[0][nt], aH0, bl);
                mma_bf16(acc[1][nt], aH1, bl);
                mma_bf16(acc[0][nt], aL0, bh);
                mma_bf16(acc[1][nt], aL1, bh);
            }
        }
        __syncthreads();
    }

    // epilogue
    int g = lid >> 2, t = lid & 3;
    const float SCALE = 0.08838834764831845f;  // 1/sqrt(128)
#pragma unroll
    for (int mt = 0; mt < 2; mt++) {
#pragma unroll
        for (int h2 = 0; h2 < 2; h2++) {
            int r = bm + wm * 32 + mt * 16 + g + h2 * 8;
#pragma unroll
            for (int nt = 0; nt < 8; nt++) {
                int c = bn + wn * 64 + nt * 8 + t * 2;
                float v0 = acc[mt][nt][h2 * 2 + 0];
                float v1 = acc[mt][nt][h2 * 2 + 1];
                size_t co = (size_t)zC + (size_t)r * ldc + c;
                if (MODE == 0) {
                    int gb = (r >> 9) << 10;
                    v0 = (v0 + e0[c]) * e1[gb + c] * SCALE;
                    v1 = (v1 + e0[c + 1]) * e1[gb + c + 1] * SCALE;
                    store_pair_bf16(Ch, Cl, co, v0, v1);
                } else if (MODE == 1) {
                    uint2 mm = *reinterpret_cast<const uint2*>(msk + (size_t)r * NN + c);
                    v0 = mm.x ? -1e9f : v0;
                    v1 = mm.y ? -1e9f : v1;
                    *reinterpret_cast<float2*>(Cf + co) = make_float2(v0, v1);
                } else if (MODE == 2) {
                    store_pair_bf16(Ch, Cl, co, v0, v1);
                } else {
                    size_t ro = (size_t)r * FF + c;
                    v0 = fmaxf(v0 + e0[c], 0.f) + e1[ro];
                    v1 = fmaxf(v1 + e0[c + 1], 0.f) + e1[ro + 1];
                    *reinterpret_cast<float2*>(Cf + co) = make_float2(v0, v1);
                }
            }
        }
    }
}

// ---------------------------------------------------------------------------
extern "C" void kernel_launch(void* const* d_in, const int* in_sizes, int n_in,
                              void* d_out, int out_size) {
    const float* x1 = (const float*)d_in[0];
    const float* x2 = (const float*)d_in[1];
    const unsigned int* mask = (const unsigned int*)d_in[4];
    const float* Wq = (const float*)d_in[5];
    const float* bq = (const float*)d_in[6];
    const float* Wl = (const float*)d_in[7];
    const float* bl = (const float*)d_in[8];

    float* out_x = (float*)d_out;
    float* out_att = (float*)d_out + ((size_t)out_size - (size_t)BB * HH * NN * NN);

    float* p_gate;
    unsigned short *x1h, *x1l, *kgh, *kgl, *qgh, *qgl, *vth, *vtl, *vbh, *vbl;
    unsigned short *wqth, *wqtl, *wlth, *wltl, *atth, *attl;
    cudaGetSymbolAddress((void**)&p_gate, g_gate);
    cudaGetSymbolAddress((void**)&x1h, g_x1h);
    cudaGetSymbolAddress((void**)&x1l, g_x1l);
    cudaGetSymbolAddress((void**)&kgh, g_kgh);
    cudaGetSymbolAddress((void**)&kgl, g_kgl);
    cudaGetSymbolAddress((void**)&qgh, g_qgh);
    cudaGetSymbolAddress((void**)&qgl, g_qgl);
    cudaGetSymbolAddress((void**)&vth, g_vth);
    cudaGetSymbolAddress((void**)&vtl, g_vtl);
    cudaGetSymbolAddress((void**)&vbh, g_vbh);
    cudaGetSymbolAddress((void**)&vbl, g_vbl);
    cudaGetSymbolAddress((void**)&wqth, g_wqth);
    cudaGetSymbolAddress((void**)&wqtl, g_wqtl);
    cudaGetSymbolAddress((void**)&wlth, g_wlth);
    cudaGetSymbolAddress((void**)&wltl, g_wltl);
    cudaGetSymbolAddress((void**)&atth, g_atth);
    cudaGetSymbolAddress((void**)&attl, g_attl);

    cudaFuncSetAttribute(mma_gemm<0>, cudaFuncAttributeMaxDynamicSharedMemorySize, SMEM_BYTES);
    cudaFuncSetAttribute(mma_gemm<1>, cudaFuncAttributeMaxDynamicSharedMemorySize, SMEM_BYTES);
    cudaFuncSetAttribute(mma_gemm<2>, cudaFuncAttributeMaxDynamicSharedMemorySize, SMEM_BYTES);
    cudaFuncSetAttribute(mma_gemm<3>, cudaFuncAttributeMaxDynamicSharedMemorySize, SMEM_BYTES);

    // 1) gate
    gate_kernel<<<BB, 1024>>>(x2, p_gate);
    // 2) conversions to bf16 hi/lo planes
    conv_x1<<<(BB * NN * FF) / 256, 256>>>(x1, p_gate, x1h, x1l, kgh, kgl);
    conv_wq<<<(FF * FF) / 256, 256>>>(Wq, wqth, wqtl);
    conv_wl<<<(FF * FF) / 256, 256>>>(Wl, wlth, wltl);
    conv_vt<<<dim3(NN / 32, DD / 32, BB * HH), dim3(32, 8)>>>(x1, vth, vtl);
    // 3) Qg = (x1 @ Wqt + bq) * gate * scale -> qg hi/lo   [16384x1024x1024]
    mma_gemm<0><<<dim3(8, 128, 1), 256, SMEM_BYTES>>>(
        x1h, x1l, 1024, 0, 0, wqth, wqtl, 1024, 0, 0, 1024,
        nullptr, qgh, qgl, 1024, 0, 0, bq, p_gate, nullptr);
    // 4) aff = Qg @ Kg^T (+mask) -> att fp32   [512x512x128] x 256
    mma_gemm<1><<<dim3(4, 4, 256), 256, SMEM_BYTES>>>(
        qgh, qgl, 1024, (long)NN * FF, DD, kgh, kgl, 1024, (long)NN * FF, DD, 128,
        out_att, nullptr, nullptr, 512, 8L * NN * NN, (long)NN * NN,
        nullptr, nullptr, mask);
    // 5) softmax (fp32 in place + bf16 planes)
    softmax_kernel<<<(BB * HH * NN) / 8, 256>>>(out_att, atth, attl);
    // 6) vb = att @ V -> vb hi/lo   [512x128x512] x 256
    mma_gemm<2><<<dim3(1, 4, 256), 256, SMEM_BYTES>>>(
        atth, attl, 512, 8L * NN * NN, (long)NN * NN, vth, vtl, 512, 8L * DD * NN, (long)DD * NN, 512,
        nullptr, vbh, vbl, 1024, (long)NN * FF, DD,
        nullptr, nullptr, nullptr);
    // 7) xout = relu(vb @ Wlt + bl) + x1   [16384x1024x1024]
    mma_gemm<3><<<dim3(8, 128, 1), 256, SMEM_BYTES>>>(
        vbh, vbl, 1024, 0, 0, wlth, wltl, 1024, 0, 0, 1024,
        out_x, nullptr, nullptr, 1024, 0, 0, bl, x1, nullptr);
}

// round 6
// speedup vs baseline: 4.9073x; 2.1199x over previous
#include <cuda_runtime.h>
#include <cuda_bf16.h>
#include <math.h>
#include <cstdint>

#define BB 32
#define NN 512
#define FF 1024
#define HH 8
#define DD 128

// ---------------------------------------------------------------------------
// Device scratch (allocation-free), single bf16 plane each
__device__ unsigned short g_x1h[BB * NN * FF];
__device__ unsigned short g_kgh[BB * NN * FF];
__device__ unsigned short g_qgh[BB * NN * FF];
__device__ unsigned short g_vth[BB * NN * FF];
__device__ unsigned short g_vbh[BB * NN * FF];
__device__ unsigned short g_wqth[FF * FF];
__device__ unsigned short g_wlth[FF * FF];
__device__ unsigned short g_atth[(size_t)BB * HH * NN * NN];
__device__ float g_gate[BB * FF];

__device__ __forceinline__ unsigned short f2bf(float v) {
    __nv_bfloat16 h = __float2bfloat16(v);
    return *reinterpret_cast<unsigned short*>(&h);
}
// packed: lo 16 bits = bf16(v0), hi = bf16(v1)
__device__ __forceinline__ uint32_t pack_bf2(float v0, float v1) {
    uint32_t r;
    asm("cvt.rn.bf16x2.f32 %0, %1, %2;" : "=r"(r) : "f"(v1), "f"(v0));
    return r;
}

__device__ __forceinline__ uint32_t smem_u32(const void* p) {
    uint32_t a;
    asm("{ .reg .u64 t; cvta.to.shared.u64 t, %1; cvt.u32.u64 %0, t; }" : "=r"(a) : "l"(p));
    return a;
}
__device__ __forceinline__ void cpa16(uint32_t dst, const void* src) {
    asm volatile("cp.async.cg.shared.global [%0], [%1], 16;" :: "r"(dst), "l"(src));
}
#define CP_COMMIT() asm volatile("cp.async.commit_group;" ::: "memory")
#define CP_WAIT(n) asm volatile("cp.async.wait_group %0;" :: "n"(n) : "memory")

__device__ __forceinline__ void ldsm4(uint32_t* r, uint32_t addr) {
    asm volatile("ldmatrix.sync.aligned.m8n8.x4.shared.b16 {%0,%1,%2,%3}, [%4];"
                 : "=r"(r[0]), "=r"(r[1]), "=r"(r[2]), "=r"(r[3]) : "r"(addr));
}
__device__ __forceinline__ void mma_bf16(float* d, const uint32_t* a, const uint32_t* b) {
    asm volatile(
        "mma.sync.aligned.m16n8k16.row.col.f32.bf16.bf16.f32 "
        "{%0,%1,%2,%3}, {%4,%5,%6,%7}, {%8,%9}, {%0,%1,%2,%3};"
        : "+f"(d[0]), "+f"(d[1]), "+f"(d[2]), "+f"(d[3])
        : "r"(a[0]), "r"(a[1]), "r"(a[2]), "r"(a[3]), "r"(b[0]), "r"(b[1]));
}

// ---------------------------------------------------------------------------
// Small kernels
__global__ void gate_kernel(const float* __restrict__ x2, float* __restrict__ gate) {
    int b = blockIdx.x;
    int f = threadIdx.x;
    const float* p = x2 + (size_t)b * NN * FF + f;
    float s = 0.f;
#pragma unroll 8
    for (int n = 0; n < NN; n++) s += p[(size_t)n * FF];
    gate[b * FF + f] = s * (1.0f / NN);
}

__global__ void conv_x1(const float* __restrict__ x1, const float* __restrict__ gate,
                        unsigned short* xh, unsigned short* kh) {
    size_t i = (size_t)blockIdx.x * 256 + threadIdx.x;
    int c = (int)(i & (FF - 1));
    int b = (int)(i >> 19);
    float v = x1[i];
    xh[i] = f2bf(v);
    kh[i] = f2bf(v * gate[b * FF + c]);
}

__global__ void conv_wq(const float* __restrict__ Wq, unsigned short* oh) {
    int idx = blockIdx.x * 256 + threadIdx.x;
    int k = idx & (FF - 1);
    int n = idx >> 10;
    int h = n >> 7, d = n & (DD - 1);
    oh[idx] = f2bf(Wq[((size_t)h * FF + k) * DD + d]);
}

__global__ void conv_wl(const float* __restrict__ Wl, unsigned short* oh) {
    int idx = blockIdx.x * 256 + threadIdx.x;
    int k = idx & (FF - 1);
    int n = idx >> 10;
    oh[idx] = f2bf(Wl[(size_t)k * FF + n]);
}

// Vt[z=(b,h)][d][m] = x1[b, m, h*128+d]
__global__ void conv_vt(const float* __restrict__ x1, unsigned short* oh) {
    __shared__ float s[32][33];
    int z = blockIdx.z, b = z >> 3, h = z & 7;
    int m0 = blockIdx.x * 32, d0 = blockIdx.y * 32;
    const float* src = x1 + (size_t)b * NN * FF + h * DD;
    int tx = threadIdx.x, ty = threadIdx.y;
#pragma unroll
    for (int i = 0; i < 32; i += 8)
        s[ty + i][tx] = src[(size_t)(m0 + ty + i) * FF + d0 + tx];
    __syncthreads();
    size_t zo = (size_t)z * DD * NN;
#pragma unroll
    for (int i = 0; i < 32; i += 8) {
        size_t o = zo + (size_t)(d0 + ty + i) * NN + m0 + tx;
        oh[o] = f2bf(s[tx][ty + i]);
    }
}

// softmax rows of att (in place, fp32) + emit bf16 plane
__global__ void softmax_kernel(float* __restrict__ att, unsigned short* __restrict__ ah) {
    int row = blockIdx.x * 8 + (threadIdx.x >> 5);
    int lane = threadIdx.x & 31;
    size_t base = (size_t)row * NN;
    float* p = att + base;
    float v[16];
    float mx = -INFINITY;
#pragma unroll
    for (int i = 0; i < 16; i++) {
        v[i] = p[lane + i * 32];
        mx = fmaxf(mx, v[i]);
    }
#pragma unroll
    for (int o = 16; o; o >>= 1) mx = fmaxf(mx, __shfl_xor_sync(0xffffffffu, mx, o));
    float s = 0.f;
#pragma unroll
    for (int i = 0; i < 16; i++) {
        v[i] = __expf(v[i] - mx);
        s += v[i];
    }
#pragma unroll
    for (int o = 16; o; o >>= 1) s += __shfl_xor_sync(0xffffffffu, s, o);
    float inv = 1.f / s;
#pragma unroll
    for (int i = 0; i < 16; i++) {
        float w = v[i] * inv;
        int c = lane + i * 32;
        p[c] = w;
        ah[base + c] = f2bf(w);
    }
}

// ---------------------------------------------------------------------------
// Warp-MMA bf16 GEMM. CTA tile 128x128, KC=64, 8 warps (4m x 2n, warp 32x64),
// double-buffered cp.async, XOR-swizzled smem (row pitch 128B, chunk^row&7).
// A[M,K], B[N,K] bf16. MODE: 0 Q-proj -> bf16; 1 aff+mask -> fp32;
// 2 att@V -> bf16; 3 relu(acc+bl)+x1 -> fp32.
#define KC 64
#define PLANE_B 16384   // 128 rows * 128 B
#define STAGE_B 32768   // A + B
#define SMEM_BYTES 65536

template <int MODE>
__global__ void __launch_bounds__(256, 2)
mma_gemm(const unsigned short* __restrict__ Ab, int lda, long sAz, long sAh2,
         const unsigned short* __restrict__ Bb, int ldb, long sBz, long sBh2,
         int K,
         float* __restrict__ Cf, unsigned short* __restrict__ Ch,
         int ldc, long sCz, long sCh2,
         const float* __restrict__ e0, const float* __restrict__ e1,
         const unsigned int* __restrict__ maskb) {
    extern __shared__ char smem[];
    uint32_t sbase = smem_u32(smem);
    int tid = threadIdx.x;
    int lid = tid & 31, wid = tid >> 5;
    int wm = wid & 3, wn = wid >> 2;

    int z = blockIdx.z;
    const unsigned short* pA = Ab + (long)(z >> 3) * sAz + (long)(z & 7) * sAh2;
    const unsigned short* pB = Bb + (long)(z >> 3) * sBz + (long)(z & 7) * sBh2;
    long zC = (long)(z >> 3) * sCz + (long)(z & 7) * sCh2;
    const unsigned int* msk = (MODE == 1) ? (maskb + (size_t)(z >> 3) * NN * NN) : nullptr;

    int bm = blockIdx.y * 128;
    int bn = blockIdx.x * 128;

    float acc[2][8][4];
#pragma unroll
    for (int i = 0; i < 2; i++)
#pragma unroll
        for (int j = 0; j < 8; j++)
#pragma unroll
            for (int k = 0; k < 4; k++) acc[i][j][k] = 0.f;

    // ldmatrix lane addressing
    int rowAl = ((lid >> 3) & 1) * 8 + (lid & 7);
    int aK = lid >> 4;
    int rowBl = ((lid >> 4) & 1) * 8 + (lid & 7);
    int bK = (lid >> 3) & 1;
    uint32_t swz = (uint32_t)(lid & 7);
    uint32_t offA = (uint32_t)(wm * 32 + rowAl) * 128;
    uint32_t offBp[4];
#pragma unroll
    for (int p = 0; p < 4; p++)
        offBp[p] = PLANE_B + (uint32_t)(wn * 64 + p * 16 + rowBl) * 128;

    // loader: 4 cp16/thread per plane (128 rows x 8 chunks)
#define LOAD_PLANE(dstoff, src, ld, row0, k0)                                   \
    {                                                                           \
        _Pragma("unroll") for (int t = 0; t < 4; t++) {                         \
            int idx = tid + t * 256;                                            \
            int row = idx >> 3, ch = idx & 7;                                   \
            uint32_t d = (dstoff) + (uint32_t)row * 128 +                       \
                         ((uint32_t)(ch ^ (row & 7)) << 4);                     \
            cpa16(d, (src) + (size_t)((row0) + row) * (ld) + (k0) + ch * 8);    \
        }                                                                       \
    }
#define LOAD_STAGE(st, k0)                                      \
    {                                                           \
        uint32_t sb_ = sbase + (uint32_t)(st) * STAGE_B;        \
        LOAD_PLANE(sb_, pA, lda, bm, k0);                       \
        LOAD_PLANE(sb_ + PLANE_B, pB, ldb, bn, k0);             \
    }

    int nch = K >> 6;
    LOAD_STAGE(0, 0);
    CP_COMMIT();

    for (int c = 0; c < nch; c++) {
        if (c + 1 < nch) {
            LOAD_STAGE((c + 1) & 1, (c + 1) * KC);
            CP_COMMIT();
            CP_WAIT(1);
        } else {
            CP_WAIT(0);
        }
        __syncthreads();

        uint32_t ss = sbase + (uint32_t)(c & 1) * STAGE_B;
#pragma unroll
        for (int s = 0; s < 4; s++) {
            uint32_t a0[4], a1[4], bF[16];
            uint32_t kchA = ((uint32_t)(2 * s + aK) ^ swz) << 4;
            uint32_t kchB = ((uint32_t)(2 * s + bK) ^ swz) << 4;
            ldsm4(a0, ss + offA + kchA);
            ldsm4(a1, ss + offA + 2048 + kchA);
#pragma unroll
            for (int p = 0; p < 4; p++) ldsm4(bF + p * 4, ss + offBp[p] + kchB);
#pragma unroll
            for (int nt = 0; nt < 8; nt++) {
                mma_bf16(acc[0][nt], a0, bF + nt * 2);
                mma_bf16(acc[1][nt], a1, bF + nt * 2);
            }
        }
        __syncthreads();
    }

    // epilogue
    int g = lid >> 2, t = lid & 3;
    const float SCALE = 0.08838834764831845f;  // 1/sqrt(128)
#pragma unroll
    for (int mt = 0; mt < 2; mt++) {
#pragma unroll
        for (int h2 = 0; h2 < 2; h2++) {
            int r = bm + wm * 32 + mt * 16 + g + h2 * 8;
#pragma unroll
            for (int nt = 0; nt < 8; nt++) {
                int c = bn + wn * 64 + nt * 8 + t * 2;
                float v0 = acc[mt][nt][h2 * 2 + 0];
                float v1 = acc[mt][nt][h2 * 2 + 1];
                size_t co = (size_t)zC + (size_t)r * ldc + c;
                if (MODE == 0) {
                    int gb = (r >> 9) << 10;
                    v0 = (v0 + e0[c]) * e1[gb + c] * SCALE;
                    v1 = (v1 + e0[c + 1]) * e1[gb + c + 1] * SCALE;
                    *reinterpret_cast<uint32_t*>(Ch + co) = pack_bf2(v0, v1);
                } else if (MODE == 1) {
                    uint2 mm = *reinterpret_cast<const uint2*>(msk + (size_t)r * NN + c);
                    v0 = mm.x ? -1e9f : v0;
                    v1 = mm.y ? -1e9f : v1;
                    *reinterpret_cast<float2*>(Cf + co) = make_float2(v0, v1);
                } else if (MODE == 2) {
                    *reinterpret_cast<uint32_t*>(Ch + co) = pack_bf2(v0, v1);
                } else {
                    size_t ro = (size_t)r * FF + c;
                    v0 = fmaxf(v0 + e0[c], 0.f) + e1[ro];
                    v1 = fmaxf(v1 + e0[c + 1], 0.f) + e1[ro + 1];
                    *reinterpret_cast<float2*>(Cf + co) = make_float2(v0, v1);
                }
            }
        }
    }
}

// ---------------------------------------------------------------------------
extern "C" void kernel_launch(void* const* d_in, const int* in_sizes, int n_in,
                              void* d_out, int out_size) {
    const float* x1 = (const float*)d_in[0];
    const float* x2 = (const float*)d_in[1];
    const unsigned int* mask = (const unsigned int*)d_in[4];
    const float* Wq = (const float*)d_in[5];
    const float* bq = (const float*)d_in[6];
    const float* Wl = (const float*)d_in[7];
    const float* bl = (const float*)d_in[8];

    float* out_x = (float*)d_out;
    float* out_att = (float*)d_out + ((size_t)out_size - (size_t)BB * HH * NN * NN);

    float* p_gate;
    unsigned short *x1h, *kgh, *qgh, *vth, *vbh, *wqth, *wlth, *atth;
    cudaGetSymbolAddress((void**)&p_gate, g_gate);
    cudaGetSymbolAddress((void**)&x1h, g_x1h);
    cudaGetSymbolAddress((void**)&kgh, g_kgh);
    cudaGetSymbolAddress((void**)&qgh, g_qgh);
    cudaGetSymbolAddress((void**)&vth, g_vth);
    cudaGetSymbolAddress((void**)&vbh, g_vbh);
    cudaGetSymbolAddress((void**)&wqth, g_wqth);
    cudaGetSymbolAddress((void**)&wlth, g_wlth);
    cudaGetSymbolAddress((void**)&atth, g_atth);

    cudaFuncSetAttribute(mma_gemm<0>, cudaFuncAttributeMaxDynamicSharedMemorySize, SMEM_BYTES);
    cudaFuncSetAttribute(mma_gemm<1>, cudaFuncAttributeMaxDynamicSharedMemorySize, SMEM_BYTES);
    cudaFuncSetAttribute(mma_gemm<2>, cudaFuncAttributeMaxDynamicSharedMemorySize, SMEM_BYTES);
    cudaFuncSetAttribute(mma_gemm<3>, cudaFuncAttributeMaxDynamicSharedMemorySize, SMEM_BYTES);

    // 1) gate
    gate_kernel<<<BB, 1024>>>(x2, p_gate);
    // 2) conversions to bf16
    conv_x1<<<(BB * NN * FF) / 256, 256>>>(x1, p_gate, x1h, kgh);
    conv_wq<<<(FF * FF) / 256, 256>>>(Wq, wqth);
    conv_wl<<<(FF * FF) / 256, 256>>>(Wl, wlth);
    conv_vt<<<dim3(NN / 32, DD / 32, BB * HH), dim3(32, 8)>>>(x1, vth);
    // 3) Qg = (x1 @ Wqt + bq) * gate * scale -> bf16   [16384x1024x1024]
    mma_gemm<0><<<dim3(8, 128, 1), 256, SMEM_BYTES>>>(
        x1h, 1024, 0, 0, wqth, 1024, 0, 0, 1024,
        nullptr, qgh, 1024, 0, 0, bq, p_gate, nullptr);
    // 4) aff = Qg @ Kg^T (+mask) -> att fp32   [512x512x128] x 256
    mma_gemm<1><<<dim3(4, 4, 256), 256, SMEM_BYTES>>>(
        qgh, 1024, (long)NN * FF, DD, kgh, 1024, (long)NN * FF, DD, 128,
        out_att, nullptr, 512, 8L * NN * NN, (long)NN * NN,
        nullptr, nullptr, mask);
    // 5) softmax (fp32 in place + bf16 plane)
    softmax_kernel<<<(BB * HH * NN) / 8, 256>>>(out_att, atth);
    // 6) vb = att @ V -> bf16   [512x128x512] x 256
    mma_gemm<2><<<dim3(1, 4, 256), 256, SMEM_BYTES>>>(
        atth, 512, 8L * NN * NN, (long)NN * NN, vth, 512, 8L * DD * NN, (long)DD * NN, 512,
        nullptr, vbh, 1024, (long)NN * FF, DD,
        nullptr, nullptr, nullptr);
    // 7) xout = relu(vb @ Wlt + bl) + x1   [16384x1024x1024]
    mma_gemm<3><<<dim3(8, 128, 1), 256, SMEM_BYTES>>>(
        vbh, 1024, 0, 0, wlth, 1024, 0, 0, 1024,
        out_x, nullptr, 1024, 0, 0, bl, x1, nullptr);
}

// round 7
// speedup vs baseline: 5.1348x; 1.0464x over previous
#include <cuda_runtime.h>
#include <cuda_bf16.h>
#include <math.h>
#include <cstdint>

#define BB 32
#define NN 512
#define FF 1024
#define HH 8
#define DD 128

// ---------------------------------------------------------------------------
// Device scratch (allocation-free), single bf16 plane each
__device__ unsigned short g_x1h[BB * NN * FF];
__device__ unsigned short g_kgh[BB * NN * FF];
__device__ unsigned short g_qgh[BB * NN * FF];
__device__ unsigned short g_vth[BB * NN * FF];
__device__ unsigned short g_vbh[BB * NN * FF];
__device__ unsigned short g_wqth[FF * FF];
__device__ unsigned short g_wlth[FF * FF];
__device__ unsigned short g_atth[(size_t)BB * HH * NN * NN];
__device__ float g_gate[BB * FF];

__device__ __forceinline__ unsigned short f2bf(float v) {
    __nv_bfloat16 h = __float2bfloat16(v);
    return *reinterpret_cast<unsigned short*>(&h);
}
// packed: lo 16 bits = bf16(v0), hi = bf16(v1)
__device__ __forceinline__ uint32_t pack_bf2(float v0, float v1) {
    uint32_t r;
    asm("cvt.rn.bf16x2.f32 %0, %1, %2;" : "=r"(r) : "f"(v1), "f"(v0));
    return r;
}

__device__ __forceinline__ uint32_t smem_u32(const void* p) {
    uint32_t a;
    asm("{ .reg .u64 t; cvta.to.shared.u64 t, %1; cvt.u32.u64 %0, t; }" : "=r"(a) : "l"(p));
    return a;
}
__device__ __forceinline__ void cpa16(uint32_t dst, const void* src) {
    asm volatile("cp.async.cg.shared.global [%0], [%1], 16;" :: "r"(dst), "l"(src));
}
#define CP_COMMIT() asm volatile("cp.async.commit_group;" ::: "memory")
#define CP_WAIT(n) asm volatile("cp.async.wait_group %0;" :: "n"(n) : "memory")

__device__ __forceinline__ void ldsm4(uint32_t* r, uint32_t addr) {
    asm volatile("ldmatrix.sync.aligned.m8n8.x4.shared.b16 {%0,%1,%2,%3}, [%4];"
                 : "=r"(r[0]), "=r"(r[1]), "=r"(r[2]), "=r"(r[3]) : "r"(addr));
}
__device__ __forceinline__ void mma_bf16(float* d, const uint32_t* a, const uint32_t* b) {
    asm volatile(
        "mma.sync.aligned.m16n8k16.row.col.f32.bf16.bf16.f32 "
        "{%0,%1,%2,%3}, {%4,%5,%6,%7}, {%8,%9}, {%0,%1,%2,%3};"
        : "+f"(d[0]), "+f"(d[1]), "+f"(d[2]), "+f"(d[3])
        : "r"(a[0]), "r"(a[1]), "r"(a[2]), "r"(a[3]), "r"(b[0]), "r"(b[1]));
}

// ---------------------------------------------------------------------------
// Small kernels
__global__ void gate_kernel(const float* __restrict__ x2, float* __restrict__ gate) {
    int b = blockIdx.x;
    int f = threadIdx.x;
    const float* p = x2 + (size_t)b * NN * FF + f;
    float s = 0.f;
#pragma unroll 8
    for (int n = 0; n < NN; n++) s += p[(size_t)n * FF];
    gate[b * FF + f] = s * (1.0f / NN);
}

__global__ void conv_x1(const float* __restrict__ x1, const float* __restrict__ gate,
                        unsigned short* xh, unsigned short* kh) {
    size_t i = (size_t)blockIdx.x * 256 + threadIdx.x;
    int c = (int)(i & (FF - 1));
    int b = (int)(i >> 19);
    float v = x1[i];
    xh[i] = f2bf(v);
    kh[i] = f2bf(v * gate[b * FF + c]);
}

// Wqt[h*128+d][f] = Wq[h][f][d]  (tiled transpose)
__global__ void conv_wq(const float* __restrict__ W, unsigned short* __restrict__ o) {
    __shared__ float s[32][33];
    int h = blockIdx.z;
    int f0 = blockIdx.x * 32, d0 = blockIdx.y * 32;
    int tx = threadIdx.x, ty = threadIdx.y;
#pragma unroll
    for (int i = 0; i < 32; i += 8)
        s[ty + i][tx] = W[((size_t)h * FF + f0 + ty + i) * DD + d0 + tx];
    __syncthreads();
#pragma unroll
    for (int i = 0; i < 32; i += 8)
        o[(size_t)(h * DD + d0 + ty + i) * FF + f0 + tx] = f2bf(s[tx][ty + i]);
}

// Wlt[n][k] = Wl[k][n]  (tiled transpose)
__global__ void conv_wl(const float* __restrict__ W, unsigned short* __restrict__ o) {
    __shared__ float s[32][33];
    int k0 = blockIdx.x * 32, n0 = blockIdx.y * 32;
    int tx = threadIdx.x, ty = threadIdx.y;
#pragma unroll
    for (int i = 0; i < 32; i += 8)
        s[ty + i][tx] = W[(size_t)(k0 + ty + i) * FF + n0 + tx];
    __syncthreads();
#pragma unroll
    for (int i = 0; i < 32; i += 8)
        o[(size_t)(n0 + ty + i) * FF + k0 + tx] = f2bf(s[tx][ty + i]);
}

// Vt[z=(b,h)][d][m] = x1[b, m, h*128+d]
__global__ void conv_vt(const float* __restrict__ x1, unsigned short* oh) {
    __shared__ float s[32][33];
    int z = blockIdx.z, b = z >> 3, h = z & 7;
    int m0 = blockIdx.x * 32, d0 = blockIdx.y * 32;
    const float* src = x1 + (size_t)b * NN * FF + h * DD;
    int tx = threadIdx.x, ty = threadIdx.y;
#pragma unroll
    for (int i = 0; i < 32; i += 8)
        s[ty + i][tx] = src[(size_t)(m0 + ty + i) * FF + d0 + tx];
    __syncthreads();
    size_t zo = (size_t)z * DD * NN;
#pragma unroll
    for (int i = 0; i < 32; i += 8) {
        size_t o = zo + (size_t)(d0 + ty + i) * NN + m0 + tx;
        oh[o] = f2bf(s[tx][ty + i]);
    }
}

// ---------------------------------------------------------------------------
// Fused aff + mask + softmax. Per z=(b,h): CTA = 64 q-rows x 512 k-cols, K=128.
// 512 threads = 16 warps (4m x 4n), warp tile 16x128. Full operands in smem.
#define FA0 0
#define FA1 8192
#define FB0 16384
#define FB1 81920
#define FRED 147456
#define FRED2 148480
#define FS_BYTES 149504

__global__ void __launch_bounds__(512, 1)
aff_softmax(const unsigned short* __restrict__ qg, const unsigned short* __restrict__ kg,
            const unsigned int* __restrict__ maskb,
            float* __restrict__ att, unsigned short* __restrict__ attb) {
    extern __shared__ char smem[];
    uint32_t sbase = smem_u32(smem);
    int tid = threadIdx.x, lid = tid & 31, wid = tid >> 5;
    int wm = wid & 3, wn = wid >> 2;
    int z = blockIdx.z, b = z >> 3;
    const unsigned short* pA = qg + (size_t)b * NN * FF + (z & 7) * DD;
    const unsigned short* pB = kg + (size_t)b * NN * FF + (z & 7) * DD;
    const unsigned int* msk = maskb + (size_t)b * NN * NN;
    size_t attz = (size_t)z * NN * NN;
    int bm = blockIdx.y * 64;

    // async loads: chunk0 (k 0-63), commit; chunk1 (k 64-127), commit
    {
        int rowA = tid >> 3, chA = tid & 7;
        uint32_t dA = (uint32_t)rowA * 128 + ((uint32_t)(chA ^ (rowA & 7)) << 4);
        const unsigned short* sA = pA + (size_t)(bm + rowA) * FF + chA * 8;
        cpa16(sbase + FA0 + dA, sA);
#pragma unroll
        for (int t = 0; t < 8; t++) {
            int idx = tid + t * 512, row = idx >> 3, ch = idx & 7;
            cpa16(sbase + FB0 + (uint32_t)row * 128 + ((uint32_t)(ch ^ (row & 7)) << 4),
                  pB + (size_t)row * FF + ch * 8);
        }
        CP_COMMIT();
        cpa16(sbase + FA1 + dA, sA + 64);
#pragma unroll
        for (int t = 0; t < 8; t++) {
            int idx = tid + t * 512, row = idx >> 3, ch = idx & 7;
            cpa16(sbase + FB1 + (uint32_t)row * 128 + ((uint32_t)(ch ^ (row & 7)) << 4),
                  pB + (size_t)row * FF + 64 + ch * 8);
        }
        CP_COMMIT();
    }

    float acc[16][4];
#pragma unroll
    for (int i = 0; i < 16; i++)
#pragma unroll
        for (int j = 0; j < 4; j++) acc[i][j] = 0.f;

    int rowAl = ((lid >> 3) & 1) * 8 + (lid & 7);
    int aK = lid >> 4;
    int rowBl = ((lid >> 4) & 1) * 8 + (lid & 7);
    int bK = (lid >> 3) & 1;
    uint32_t swz = (uint32_t)(lid & 7);
    uint32_t offA = (uint32_t)(wm * 16 + rowAl) * 128;
    uint32_t offB = (uint32_t)(wn * 128 + rowBl) * 128;

    CP_WAIT(1);
    __syncthreads();
#pragma unroll
    for (int ck = 0; ck < 2; ck++) {
        uint32_t cA = sbase + (ck ? FA1 : FA0);
        uint32_t cB = sbase + (ck ? FB1 : FB0);
#pragma unroll
        for (int s = 0; s < 4; s++) {
            uint32_t a[4];
            ldsm4(a, cA + offA + (((uint32_t)(2 * s + aK) ^ swz) << 4));
            uint32_t kb = ((uint32_t)(2 * s + bK) ^ swz) << 4;
#pragma unroll
            for (int p = 0; p < 8; p++) {
                uint32_t bf[4];
                ldsm4(bf, cB + offB + (uint32_t)p * 2048 + kb);
                mma_bf16(acc[2 * p], a, bf);
                mma_bf16(acc[2 * p + 1], a, bf + 2);
            }
        }
        if (ck == 0) {
            CP_WAIT(0);
            __syncthreads();
        }
    }

    // ---- fused mask + softmax epilogue ----
    int g = lid >> 2, t = lid & 3;
    int lr = wm * 16 + g;          // local rows lr, lr+8
    int r0 = bm + lr, r1 = r0 + 8;
    float* rmax = reinterpret_cast<float*>(smem + FRED);
    float* rsum = reinterpret_cast<float*>(smem + FRED2);

    float mx0 = -INFINITY, mx1 = -INFINITY;
#pragma unroll
    for (int nf = 0; nf < 16; nf++) {
        int c = wn * 128 + nf * 8 + t * 2;
        uint2 m0 = *reinterpret_cast<const uint2*>(msk + (size_t)r0 * NN + c);
        uint2 m1 = *reinterpret_cast<const uint2*>(msk + (size_t)r1 * NN + c);
        if (m0.x) acc[nf][0] = -1e9f;
        if (m0.y) acc[nf][1] = -1e9f;
        if (m1.x) acc[nf][2] = -1e9f;
        if (m1.y) acc[nf][3] = -1e9f;
        mx0 = fmaxf(mx0, fmaxf(acc[nf][0], acc[nf][1]));
        mx1 = fmaxf(mx1, fmaxf(acc[nf][2], acc[nf][3]));
    }
    mx0 = fmaxf(mx0, __shfl_xor_sync(0xffffffffu, mx0, 1));
    mx0 = fmaxf(mx0, __shfl_xor_sync(0xffffffffu, mx0, 2));
    mx1 = fmaxf(mx1, __shfl_xor_sync(0xffffffffu, mx1, 1));
    mx1 = fmaxf(mx1, __shfl_xor_sync(0xffffffffu, mx1, 2));
    if (t == 0) {
        rmax[lr * 4 + wn] = mx0;
        rmax[(lr + 8) * 4 + wn] = mx1;
    }
    __syncthreads();
    {
        float4 q0 = *reinterpret_cast<float4*>(rmax + lr * 4);
        float4 q1 = *reinterpret_cast<float4*>(rmax + (lr + 8) * 4);
        mx0 = fmaxf(fmaxf(q0.x, q0.y), fmaxf(q0.z, q0.w));
        mx1 = fmaxf(fmaxf(q1.x, q1.y), fmaxf(q1.z, q1.w));
    }
    float s0 = 0.f, s1 = 0.f;
#pragma unroll
    for (int nf = 0; nf < 16; nf++) {
        acc[nf][0] = __expf(acc[nf][0] - mx0);
        acc[nf][1] = __expf(acc[nf][1] - mx0);
        acc[nf][2] = __expf(acc[nf][2] - mx1);
        acc[nf][3] = __expf(acc[nf][3] - mx1);
        s0 += acc[nf][0] + acc[nf][1];
        s1 += acc[nf][2] + acc[nf][3];
    }
    s0 += __shfl_xor_sync(0xffffffffu, s0, 1);
    s0 += __shfl_xor_sync(0xffffffffu, s0, 2);
    s1 += __shfl_xor_sync(0xffffffffu, s1, 1);
    s1 += __shfl_xor_sync(0xffffffffu, s1, 2);
    if (t == 0) {
        rsum[lr * 4 + wn] = s0;
        rsum[(lr + 8) * 4 + wn] = s1;
    }
    __syncthreads();
    float inv0, inv1;
    {
        float4 q0 = *reinterpret_cast<float4*>(rsum + lr * 4);
        float4 q1 = *reinterpret_cast<float4*>(rsum + (lr + 8) * 4);
        inv0 = 1.f / (q0.x + q0.y + q0.z + q0.w);
        inv1 = 1.f / (q1.x + q1.y + q1.z + q1.w);
    }
#pragma unroll
    for (int nf = 0; nf < 16; nf++) {
        int c = wn * 128 + nf * 8 + t * 2;
        float v0 = acc[nf][0] * inv0, v1 = acc[nf][1] * inv0;
        float v2 = acc[nf][2] * inv1, v3 = acc[nf][3] * inv1;
        *reinterpret_cast<float2*>(att + attz + (size_t)r0 * NN + c) = make_float2(v0, v1);
        *reinterpret_cast<float2*>(att + attz + (size_t)r1 * NN + c) = make_float2(v2, v3);
        *reinterpret_cast<uint32_t*>(attb + attz + (size_t)r0 * NN + c) = pack_bf2(v0, v1);
        *reinterpret_cast<uint32_t*>(attb + attz + (size_t)r1 * NN + c) = pack_bf2(v2, v3);
    }
}

// ---------------------------------------------------------------------------
// Warp-MMA bf16 GEMM. CTA tile 128x128, KC=64, 8 warps (4m x 2n, warp 32x64),
// double-buffered cp.async, XOR-swizzled smem (row pitch 128B, chunk^row&7).
// A[M,K], B[N,K] bf16. MODE: 0 Q-proj -> bf16; 2 att@V -> bf16;
// 3 relu(acc+bl)+x1 -> fp32.
#define KC 64
#define PLANE_B 16384   // 128 rows * 128 B
#define STAGE_B 32768   // A + B
#define SMEM_BYTES 65536

template <int MODE>
__global__ void __launch_bounds__(256, 2)
mma_gemm(const unsigned short* __restrict__ Ab, int lda, long sAz, long sAh2,
         const unsigned short* __restrict__ Bb, int ldb, long sBz, long sBh2,
         int K,
         float* __restrict__ Cf, unsigned short* __restrict__ Ch,
         int ldc, long sCz, long sCh2,
         const float* __restrict__ e0, const float* __restrict__ e1) {
    extern __shared__ char smem[];
    uint32_t sbase = smem_u32(smem);
    int tid = threadIdx.x;
    int lid = tid & 31, wid = tid >> 5;
    int wm = wid & 3, wn = wid >> 2;

    int z = blockIdx.z;
    const unsigned short* pA = Ab + (long)(z >> 3) * sAz + (long)(z & 7) * sAh2;
    const unsigned short* pB = Bb + (long)(z >> 3) * sBz + (long)(z & 7) * sBh2;
    long zC = (long)(z >> 3) * sCz + (long)(z & 7) * sCh2;

    int bm = blockIdx.y * 128;
    int bn = blockIdx.x * 128;

    float acc[2][8][4];
#pragma unroll
    for (int i = 0; i < 2; i++)
#pragma unroll
        for (int j = 0; j < 8; j++)
#pragma unroll
            for (int k = 0; k < 4; k++) acc[i][j][k] = 0.f;

    int rowAl = ((lid >> 3) & 1) * 8 + (lid & 7);
    int aK = lid >> 4;
    int rowBl = ((lid >> 4) & 1) * 8 + (lid & 7);
    int bK = (lid >> 3) & 1;
    uint32_t swz = (uint32_t)(lid & 7);
    uint32_t offA = (uint32_t)(wm * 32 + rowAl) * 128;
    uint32_t offBp[4];
#pragma unroll
    for (int p = 0; p < 4; p++)
        offBp[p] = PLANE_B + (uint32_t)(wn * 64 + p * 16 + rowBl) * 128;

#define LOAD_PLANE(dstoff, src, ld, row0, k0)                                   \
    {                                                                           \
        _Pragma("unroll") for (int t = 0; t < 4; t++) {                         \
            int idx = tid + t * 256;                                            \
            int row = idx >> 3, ch = idx & 7;                                   \
            uint32_t d = (dstoff) + (uint32_t)row * 128 +                       \
                         ((uint32_t)(ch ^ (row & 7)) << 4);                     \
            cpa16(d, (src) + (size_t)((row0) + row) * (ld) + (k0) + ch * 8);    \
        }                                                                       \
    }
#define LOAD_STAGE(st, k0)                                      \
    {                                                           \
        uint32_t sb_ = sbase + (uint32_t)(st) * STAGE_B;        \
        LOAD_PLANE(sb_, pA, lda, bm, k0);                       \
        LOAD_PLANE(sb_ + PLANE_B, pB, ldb, bn, k0);             \
    }

    int nch = K >> 6;
    LOAD_STAGE(0, 0);
    CP_COMMIT();

    for (int c = 0; c < nch; c++) {
        if (c + 1 < nch) {
            LOAD_STAGE((c + 1) & 1, (c + 1) * KC);
            CP_COMMIT();
            CP_WAIT(1);
        } else {
            CP_WAIT(0);
        }
        __syncthreads();

        uint32_t ss = sbase + (uint32_t)(c & 1) * STAGE_B;
#pragma unroll
        for (int s = 0; s < 4; s++) {
            uint32_t a0[4], a1[4], bF[16];
            uint32_t kchA = ((uint32_t)(2 * s + aK) ^ swz) << 4;
            uint32_t kchB = ((uint32_t)(2 * s + bK) ^ swz) << 4;
            ldsm4(a0, ss + offA + kchA);
            ldsm4(a1, ss + offA + 2048 + kchA);
#pragma unroll
            for (int p = 0; p < 4; p++) ldsm4(bF + p * 4, ss + offBp[p] + kchB);
#pragma unroll
            for (int nt = 0; nt < 8; nt++) {
                mma_bf16(acc[0][nt], a0, bF + nt * 2);
                mma_bf16(acc[1][nt], a1, bF + nt * 2);
            }
        }
        __syncthreads();
    }

    // epilogue
    int g = lid >> 2, t = lid & 3;
    const float SCALE = 0.08838834764831845f;  // 1/sqrt(128)
#pragma unroll
    for (int mt = 0; mt < 2; mt++) {
#pragma unroll
        for (int h2 = 0; h2 < 2; h2++) {
            int r = bm + wm * 32 + mt * 16 + g + h2 * 8;
#pragma unroll
            for (int nt = 0; nt < 8; nt++) {
                int c = bn + wn * 64 + nt * 8 + t * 2;
                float v0 = acc[mt][nt][h2 * 2 + 0];
                float v1 = acc[mt][nt][h2 * 2 + 1];
                size_t co = (size_t)zC + (size_t)r * ldc + c;
                if (MODE == 0) {
                    int gb = (r >> 9) << 10;
                    v0 = (v0 + e0[c]) * e1[gb + c] * SCALE;
                    v1 = (v1 + e0[c + 1]) * e1[gb + c + 1] * SCALE;
                    *reinterpret_cast<uint32_t*>(Ch + co) = pack_bf2(v0, v1);
                } else if (MODE == 2) {
                    *reinterpret_cast<uint32_t*>(Ch + co) = pack_bf2(v0, v1);
                } else {
                    size_t ro = (size_t)r * FF + c;
                    v0 = fmaxf(v0 + e0[c], 0.f) + e1[ro];
                    v1 = fmaxf(v1 + e0[c + 1], 0.f) + e1[ro + 1];
                    *reinterpret_cast<float2*>(Cf + co) = make_float2(v0, v1);
                }
            }
        }
    }
}

// ---------------------------------------------------------------------------
extern "C" void kernel_launch(void* const* d_in, const int* in_sizes, int n_in,
                              void* d_out, int out_size) {
    const float* x1 = (const float*)d_in[0];
    const float* x2 = (const float*)d_in[1];
    const unsigned int* mask = (const unsigned int*)d_in[4];
    const float* Wq = (const float*)d_in[5];
    const float* bq = (const float*)d_in[6];
    const float* Wl = (const float*)d_in[7];
    const float* bl = (const float*)d_in[8];

    float* out_x = (float*)d_out;
    float* out_att = (float*)d_out + ((size_t)out_size - (size_t)BB * HH * NN * NN);

    float* p_gate;
    unsigned short *x1h, *kgh, *qgh, *vth, *vbh, *wqth, *wlth, *atth;
    cudaGetSymbolAddress((void**)&p_gate, g_gate);
    cudaGetSymbolAddress((void**)&x1h, g_x1h);
    cudaGetSymbolAddress((void**)&kgh, g_kgh);
    cudaGetSymbolAddress((void**)&qgh, g_qgh);
    cudaGetSymbolAddress((void**)&vth, g_vth);
    cudaGetSymbolAddress((void**)&vbh, g_vbh);
    cudaGetSymbolAddress((void**)&wqth, g_wqth);
    cudaGetSymbolAddress((void**)&wlth, g_wlth);
    cudaGetSymbolAddress((void**)&atth, g_atth);

    cudaFuncSetAttribute(mma_gemm<0>, cudaFuncAttributeMaxDynamicSharedMemorySize, SMEM_BYTES);
    cudaFuncSetAttribute(mma_gemm<2>, cudaFuncAttributeMaxDynamicSharedMemorySize, SMEM_BYTES);
    cudaFuncSetAttribute(mma_gemm<3>, cudaFuncAttributeMaxDynamicSharedMemorySize, SMEM_BYTES);
    cudaFuncSetAttribute(aff_softmax, cudaFuncAttributeMaxDynamicSharedMemorySize, FS_BYTES);

    // 1) gate
    gate_kernel<<<BB, 1024>>>(x2, p_gate);
    // 2) conversions to bf16
    conv_x1<<<(BB * NN * FF) / 256, 256>>>(x1, p_gate, x1h, kgh);
    conv_wq<<<dim3(FF / 32, DD / 32, HH), dim3(32, 8)>>>(Wq, wqth);
    conv_wl<<<dim3(FF / 32, FF / 32), dim3(32, 8)>>>(Wl, wlth);
    conv_vt<<<dim3(NN / 32, DD / 32, BB * HH), dim3(32, 8)>>>(x1, vth);
    // 3) Qg = (x1 @ Wqt + bq) * gate * scale -> bf16   [16384x1024x1024]
    mma_gemm<0><<<dim3(8, 128, 1), 256, SMEM_BYTES>>>(
        x1h, 1024, 0, 0, wqth, 1024, 0, 0, 1024,
        nullptr, qgh, 1024, 0, 0, bq, p_gate);
    // 4) fused aff + mask + softmax -> att fp32 (output) + att bf16
    aff_softmax<<<dim3(1, NN / 64, BB * HH), 512, FS_BYTES>>>(
        qgh, kgh, mask, out_att, atth);
    // 5) vb = att @ V -> bf16   [512x128x512] x 256
    mma_gemm<2><<<dim3(1, 4, 256), 256, SMEM_BYTES>>>(
        atth, 512, 8L * NN * NN, (long)NN * NN, vth, 512, 8L * DD * NN, (long)DD * NN, 512,
        nullptr, vbh, 1024, (long)NN * FF, DD,
        nullptr, nullptr);
    // 6) xout = relu(vb @ Wlt + bl) + x1   [16384x1024x1024]
    mma_gemm<3><<<dim3(8, 128, 1), 256, SMEM_BYTES>>>(
        vbh, 1024, 0, 0, wlth, 1024, 0, 0, 1024,
        out_x, nullptr, 1024, 0, 0, bl, x1);
}